// round 5
// baseline (speedup 1.0000x reference)
#include <cuda_runtime.h>

#define NB      8
#define T_DIM   8
#define BT      64          // NB*T
#define NPTS    6890
#define KCLS    7
#define CCH     128
#define DSUM    512
#define H1      128
#define H2      64
#define PCA_D   64
#define V3      23106       // 7702*3
#define NWORDS  216         // ceil(NPTS/32)
#define TPAD    (CCH + 4)   // smem row pitch: 16B-aligned, 4-bank rotation

// Scratch (no allocation allowed in kernel_launch)
__device__ unsigned g_mask[BT * NWORDS];
__device__ int      g_idx[BT * NPTS];
__device__ int      g_count[BT];
__device__ float    g_coeff[NB * PCA_D];

// ---------------------------------------------------------------------------
// Kernel 1a: full-grid argmax -> ballot -> bitmask words.
// ---------------------------------------------------------------------------
__global__ void mask_k(const float* __restrict__ logits,
                       const int*   __restrict__ glab)
{
    const int b = blockIdx.y;
    const int i = blockIdx.x * 256 + threadIdx.x;
    const int label = glab[0];

    bool m = false;
    if (i < NPTS) {
        const float* p = logits + ((long)b * NPTS + i) * KCLS;
        float best = __ldg(p);
        int   bi   = 0;
        #pragma unroll
        for (int k = 1; k < KCLS; k++) {
            float v = __ldg(p + k);
            if (v > best) { best = v; bi = k; }
        }
        m = (bi == label);
    }
    const unsigned bal = __ballot_sync(0xffffffffu, m);
    if ((threadIdx.x & 31) == 0) {
        const int w = (blockIdx.x * 256 + threadIdx.x) >> 5;
        if (w < NWORDS) g_mask[b * NWORDS + w] = bal;
    }
}

// ---------------------------------------------------------------------------
// Kernel 1b: per-batch scan of mask words -> stable ascending index list.
// ---------------------------------------------------------------------------
__global__ void scan_k(int n)
{
    const int b = blockIdx.x;
    const int t = threadIdx.x;
    __shared__ int woff[8];

    unsigned word = (t < NWORDS) ? g_mask[b * NWORDS + t] : 0u;
    int cnt = __popc(word);

    int inc = cnt;                         // warp inclusive scan
    #pragma unroll
    for (int d = 1; d < 32; d <<= 1) {
        int v = __shfl_up_sync(0xffffffffu, inc, d);
        if ((t & 31) >= d) inc += v;
    }
    if ((t & 31) == 31) woff[t >> 5] = inc;
    __syncthreads();
    if (t < 8) {
        int v = woff[t];
        #pragma unroll
        for (int d = 1; d < 8; d <<= 1) {
            int u = __shfl_up_sync(0xffu, v, d);
            if (t >= d) v += u;
        }
        woff[t] = v;                        // inclusive over warps
    }
    __syncthreads();

    int base = inc - cnt;
    if (t >= 32) base += woff[(t >> 5) - 1];

    unsigned w = word;
    int pos = base;
    while (w) {
        const int bit = __ffs(w) - 1;
        w &= w - 1;
        if (pos < n) g_idx[b * NPTS + pos] = (t << 5) + bit;
        pos++;
    }

    if (t == 255) g_count[b] = woff[7];
}

// ---------------------------------------------------------------------------
// Kernel 2: gather + transpose.  Block = (b, 32-j tile), 256 threads.
// Phase A: 16 front-batched scattered LDGs into registers (MLP_p1 = 16).
// Phase B: STS into padded smem tile.  Phase C: coalesced float4 STG.
// ---------------------------------------------------------------------------
__global__ void gather_k(const float* __restrict__ feat,
                         const float* __restrict__ x,
                         float* __restrict__ gv,
                         float* __restrict__ gf,
                         int n)
{
    const int b  = blockIdx.y;
    const int j0 = blockIdx.x * 32;
    if (j0 >= n) return;
    const int t = threadIdx.x;

    __shared__ float tile[32][TPAD];
    __shared__ int   sidx[32];

    int cnt = g_count[b];
    if (cnt > n) cnt = n;

    if (t < 32) {
        const int j = j0 + t;
        sidx[t] = (j < cnt) ? g_idx[b * NPTS + j] : -1;
    }
    __syncthreads();

    const int lane = t & 31;
    const int w    = t >> 5;
    const int idx  = sidx[lane];
    const float* fb = feat + (long)b * CCH * NPTS;

    // Phase A: all 16 independent loads issued before any consumer.
    float r[CCH / 8];
    if (idx >= 0) {
        const float* p = fb + idx + (long)w * NPTS;
        #pragma unroll
        for (int it = 0; it < CCH / 8; it++)
            r[it] = __ldg(p + (long)(it * 8) * NPTS);
    } else {
        #pragma unroll
        for (int it = 0; it < CCH / 8; it++) r[it] = 0.0f;
    }
    // Phase B: stores (consume results in issue order).
    #pragma unroll
    for (int it = 0; it < CCH / 8; it++)
        tile[lane][w + it * 8] = r[it];
    __syncthreads();

    // Phase C: 32*128 floats = 1024 float4; 256 threads -> 4 iters, STG.128.
    const long gfb = ((long)b * n + j0) * CCH;
    #pragma unroll
    for (int e = t; e < 32 * (CCH / 4); e += 256) {
        const int j  = e >> 5;          // 0..31
        const int c4 = e & 31;          // float4 index within row
        if (j0 + j < n) {
            float4 v = *reinterpret_cast<const float4*>(&tile[j][c4 * 4]);
            *reinterpret_cast<float4*>(&gf[gfb + (long)j * CCH + c4 * 4]) = v;
        }
    }

    if (t < 96) {
        const int j = t / 3;
        const int k = t - j * 3;
        if (j0 + j < n) {
            const int id2 = sidx[j];
            gv[((long)b * n + (j0 + j)) * 3 + k] =
                (id2 >= 0) ? __ldg(x + ((long)b * NPTS + id2) * 3 + k) : 0.0f;
        }
    }
}

// ---------------------------------------------------------------------------
// Kernel 3: max-over-T + 3-layer MLP with eval-mode BN. Single 1024-thr block.
// ---------------------------------------------------------------------------
__global__ void mlp_k(const float* __restrict__ summ,
                      const float* __restrict__ W1, const float* __restrict__ b1,
                      const float* __restrict__ g1, const float* __restrict__ be1,
                      const float* __restrict__ rm1, const float* __restrict__ rv1,
                      const float* __restrict__ W2, const float* __restrict__ b2,
                      const float* __restrict__ g2, const float* __restrict__ be2,
                      const float* __restrict__ rm2, const float* __restrict__ rv2,
                      const float* __restrict__ W3, const float* __restrict__ b3,
                      float* __restrict__ coeff_out)
{
    __shared__ float gs [NB * DSUM];
    __shared__ float h1s[NB * H1];
    __shared__ float h2s[NB * H2];
    const int t = threadIdx.x;

    for (int i = t; i < NB * DSUM; i += 1024) {
        const int nb = i / DSUM;
        const int d  = i - nb * DSUM;
        float m = summ[(long)(nb * T_DIM) * DSUM + d];
        #pragma unroll
        for (int tt = 1; tt < T_DIM; tt++)
            m = fmaxf(m, summ[(long)(nb * T_DIM + tt) * DSUM + d]);
        gs[i] = m;
    }
    __syncthreads();

    {   // h1: 1024 threads == NB*H1
        const int nb = t >> 7;
        const int j  = t & 127;
        float acc = 0.0f;
        const float* wr = W1 + (long)j * DSUM;
        const float* gr = gs + nb * DSUM;
        #pragma unroll 4
        for (int d = 0; d < DSUM; d++) acc = fmaf(gr[d], wr[d], acc);
        acc += b1[j];
        acc = (acc - rm1[j]) * rsqrtf(rv1[j] + 1e-5f) * g1[j] + be1[j];
        h1s[nb * H1 + j] = fmaxf(acc, 0.0f);
    }
    __syncthreads();

    if (t < NB * H2) {
        const int nb = t >> 6;
        const int j  = t & 63;
        float acc = 0.0f;
        const float* wr = W2 + (long)j * H1;
        const float* hr = h1s + nb * H1;
        #pragma unroll 4
        for (int d = 0; d < H1; d++) acc = fmaf(hr[d], wr[d], acc);
        acc += b2[j];
        acc = (acc - rm2[j]) * rsqrtf(rv2[j] + 1e-5f) * g2[j] + be2[j];
        h2s[nb * H2 + j] = fmaxf(acc, 0.0f);
    }
    __syncthreads();

    if (t < NB * PCA_D) {
        const int nb = t >> 6;
        const int j  = t & 63;
        float acc = b3[j];
        const float* wr = W3 + (long)j * H2;
        const float* hr = h2s + nb * H2;
        #pragma unroll 4
        for (int d = 0; d < H2; d++) acc = fmaf(hr[d], wr[d], acc);
        g_coeff[nb * PCA_D + j] = acc;
        coeff_out[nb * PCA_D + j] = acc;
    }
}

// ---------------------------------------------------------------------------
// Kernel 4: tpose = (coeff @ pca_comp + mean) * scale.  Two columns per
// thread (float2), comp read once coalesced.
// ---------------------------------------------------------------------------
__global__ void tpose_k(const float* __restrict__ comp,
                        const float* __restrict__ mean,
                        const float* __restrict__ scale,
                        float* __restrict__ out)
{
    __shared__ float sc[NB * PCA_D];
    const int t = threadIdx.x;
    for (int i = t; i < NB * PCA_D; i += 256) sc[i] = g_coeff[i];
    __syncthreads();

    const int d2 = blockIdx.x * 256 + t;          // float2 column index
    if (d2 >= V3 / 2) return;
    const int d = d2 * 2;

    float accx[NB], accy[NB];
    #pragma unroll
    for (int nb = 0; nb < NB; nb++) { accx[nb] = 0.0f; accy[nb] = 0.0f; }

    #pragma unroll 4
    for (int k = 0; k < PCA_D; k++) {
        const float2 w = *reinterpret_cast<const float2*>(comp + (long)k * V3 + d);
        #pragma unroll
        for (int nb = 0; nb < NB; nb++) {
            const float c = sc[nb * PCA_D + k];
            accx[nb] = fmaf(c, w.x, accx[nb]);
            accy[nb] = fmaf(c, w.y, accy[nb]);
        }
    }
    const float2 mn = *reinterpret_cast<const float2*>(mean + d);
    const float2 s  = *reinterpret_cast<const float2*>(scale + d);
    #pragma unroll
    for (int nb = 0; nb < NB; nb++) {
        float2 o;
        o.x = (accx[nb] + mn.x) * s.x;
        o.y = (accy[nb] + mn.y) * s.y;
        *reinterpret_cast<float2*>(out + (long)nb * V3 + d) = o;
    }
}

// ---------------------------------------------------------------------------
extern "C" void kernel_launch(void* const* d_in, const int* in_sizes, int n_in,
                              void* d_out, int out_size)
{
    const float* x      = (const float*)d_in[0];
    const float* logits = (const float*)d_in[1];
    const float* feat   = (const float*)d_in[2];
    const float* summ   = (const float*)d_in[3];
    const float* W1  = (const float*)d_in[4];
    const float* b1  = (const float*)d_in[5];
    const float* g1  = (const float*)d_in[6];
    const float* be1 = (const float*)d_in[7];
    const float* rm1 = (const float*)d_in[8];
    const float* rv1 = (const float*)d_in[9];
    const float* W2  = (const float*)d_in[10];
    const float* b2  = (const float*)d_in[11];
    const float* g2  = (const float*)d_in[12];
    const float* be2 = (const float*)d_in[13];
    const float* rm2 = (const float*)d_in[14];
    const float* rv2 = (const float*)d_in[15];
    const float* W3  = (const float*)d_in[16];
    const float* b3  = (const float*)d_in[17];
    const float* comp  = (const float*)d_in[18];
    const float* mean  = (const float*)d_in[19];
    const float* scale = (const float*)d_in[20];
    const int*   glab  = (const int*)d_in[21];

    // Derive n from out_size: out = BT*n*(3+CCH) + NB*PCA_D + NB*V3
    const int n = (out_size - NB * PCA_D - NB * V3) / (BT * (3 + CCH));

    float* gv    = (float*)d_out;
    float* gf    = gv + (long)BT * n * 3;
    float* coeff = gf + (long)BT * n * CCH;
    float* tpose = coeff + NB * PCA_D;

    mask_k<<<dim3((NPTS + 255) / 256, BT), 256>>>(logits, glab);
    scan_k<<<BT, 256>>>(n);
    gather_k<<<dim3((n + 31) / 32, BT), 256>>>(feat, x, gv, gf, n);
    mlp_k<<<1, 1024>>>(summ, W1, b1, g1, be1, rm1, rv1,
                       W2, b2, g2, be2, rm2, rv2, W3, b3, coeff);
    tpose_k<<<(V3 / 2 + 255) / 256, 256>>>(comp, mean, scale, tpose);
}

// round 10
// speedup vs baseline: 4.2212x; 4.2212x over previous
#include <cuda_runtime.h>

#define NB      8
#define T_DIM   8
#define BT      64          // NB*T
#define NPTS    6890
#define KCLS    7
#define CCH     128
#define DSUM    512
#define H1      128
#define H2      64
#define PCA_D   64
#define V3      23106       // 7702*3
#define NWORDS  216         // ceil(NPTS/32)
#define NCHUNK  27          // ceil(NPTS/256)
#define TPAD    (CCH + 4)   // smem row pitch: 16B-aligned, 4-bank rotation

// Scratch (no allocation allowed in kernel_launch)
__device__ int      g_idx[BT * NPTS];
__device__ int      g_count[BT];
__device__ float    g_gs[NB * DSUM];
__device__ float    g_h1[NB * H1];
__device__ float    g_h2[NB * H2];
__device__ float    g_coeff[NB * PCA_D];

// ---------------------------------------------------------------------------
// Kernel 1: fused argmax-mask + stable compaction.  One block per batch.
// Phase 1: 27 chunk ballots -> smem words (no inter-chunk barriers).
// Phase 2: 216-word scan -> stable ascending index list.
// ---------------------------------------------------------------------------
__global__ void compact2_k(const float* __restrict__ logits,
                           const int*   __restrict__ glab,
                           int n)
{
    const int b = blockIdx.x;
    const int t = threadIdx.x;
    __shared__ unsigned words[NWORDS];
    __shared__ int woff[8];

    const int label = glab[0];
    const float* lp = logits + (long)b * NPTS * KCLS;

    // Phase 1: ballots.  Warps stream chunks independently (no barriers).
    #pragma unroll 1
    for (int c = 0; c < NCHUNK; c++) {
        const int i = c * 256 + t;
        bool m = false;
        if (i < NPTS) {
            const float* p = lp + (long)i * KCLS;
            float best = __ldg(p);
            int   bi   = 0;
            #pragma unroll
            for (int k = 1; k < KCLS; k++) {
                float v = __ldg(p + k);
                if (v > best) { best = v; bi = k; }
            }
            m = (bi == label);
        }
        const unsigned bal = __ballot_sync(0xffffffffu, m);
        if ((t & 31) == 0) {
            const int w = (c * 256 + t) >> 5;
            if (w < NWORDS) words[w] = bal;
        }
    }
    __syncthreads();

    // Phase 2: scan 216 words (thread t owns word t).
    unsigned word = (t < NWORDS) ? words[t] : 0u;
    int cnt = __popc(word);

    int inc = cnt;                         // warp inclusive scan
    #pragma unroll
    for (int d = 1; d < 32; d <<= 1) {
        int v = __shfl_up_sync(0xffffffffu, inc, d);
        if ((t & 31) >= d) inc += v;
    }
    if ((t & 31) == 31) woff[t >> 5] = inc;
    __syncthreads();
    if (t < 8) {
        int v = woff[t];
        #pragma unroll
        for (int d = 1; d < 8; d <<= 1) {
            int u = __shfl_up_sync(0xffu, v, d);
            if (t >= d) v += u;
        }
        woff[t] = v;                        // inclusive over warps
    }
    __syncthreads();

    int base = inc - cnt;
    if (t >= 32) base += woff[(t >> 5) - 1];

    unsigned w = word;
    int pos = base;
    while (w) {
        const int bit = __ffs(w) - 1;
        w &= w - 1;
        if (pos < n) g_idx[b * NPTS + pos] = (t << 5) + bit;
        pos++;
    }

    if (t == 255) g_count[b] = woff[7];
}

// ---------------------------------------------------------------------------
// Kernel 2: gather + transpose.  Block = (b, 32-j tile), 256 threads.
// ---------------------------------------------------------------------------
__global__ void gather_k(const float* __restrict__ feat,
                         const float* __restrict__ x,
                         float* __restrict__ gv,
                         float* __restrict__ gf,
                         int n)
{
    const int b  = blockIdx.y;
    const int j0 = blockIdx.x * 32;
    if (j0 >= n) return;
    const int t = threadIdx.x;

    __shared__ float tile[32][TPAD];
    __shared__ int   sidx[32];

    int cnt = g_count[b];
    if (cnt > n) cnt = n;

    if (t < 32) {
        const int j = j0 + t;
        sidx[t] = (j < cnt) ? g_idx[b * NPTS + j] : -1;
    }
    __syncthreads();

    const int lane = t & 31;
    const int w    = t >> 5;
    const int idx  = sidx[lane];
    const float* fb = feat + (long)b * CCH * NPTS;

    // Phase A: all 16 independent loads issued before any consumer.
    float r[CCH / 8];
    if (idx >= 0) {
        const float* p = fb + idx + (long)w * NPTS;
        #pragma unroll
        for (int it = 0; it < CCH / 8; it++)
            r[it] = __ldg(p + (long)(it * 8) * NPTS);
    } else {
        #pragma unroll
        for (int it = 0; it < CCH / 8; it++) r[it] = 0.0f;
    }
    #pragma unroll
    for (int it = 0; it < CCH / 8; it++)
        tile[lane][w + it * 8] = r[it];
    __syncthreads();

    // Coalesced float4 stores.
    const long gfb = ((long)b * n + j0) * CCH;
    #pragma unroll
    for (int e = t; e < 32 * (CCH / 4); e += 256) {
        const int j  = e >> 5;
        const int c4 = e & 31;
        if (j0 + j < n) {
            float4 v = *reinterpret_cast<const float4*>(&tile[j][c4 * 4]);
            *reinterpret_cast<float4*>(&gf[gfb + (long)j * CCH + c4 * 4]) = v;
        }
    }

    if (t < 96) {
        const int j = t / 3;
        const int k = t - j * 3;
        if (j0 + j < n) {
            const int id2 = sidx[j];
            gv[((long)b * n + (j0 + j)) * 3 + k] =
                (id2 >= 0) ? __ldg(x + ((long)b * NPTS + id2) * 3 + k) : 0.0f;
        }
    }
}

// ---------------------------------------------------------------------------
// MLP stage, grid-parallel with coalesced warp-per-output dot products.
// ---------------------------------------------------------------------------
// gs = max over T of garment_summary.  [NB, DSUM], coalesced in d.
__global__ void gs_k(const float* __restrict__ summ)
{
    const int i = blockIdx.x * 256 + threadIdx.x;
    if (i >= NB * DSUM) return;
    const int nb = i >> 9;          // /DSUM
    const int d  = i & (DSUM - 1);
    float m = __ldg(summ + (long)(nb * T_DIM) * DSUM + d);
    #pragma unroll
    for (int tt = 1; tt < T_DIM; tt++)
        m = fmaxf(m, __ldg(summ + (long)(nb * T_DIM + tt) * DSUM + d));
    g_gs[i] = m;
}

__device__ __forceinline__ float warp_sum(float v)
{
    #pragma unroll
    for (int d = 16; d > 0; d >>= 1)
        v += __shfl_xor_sync(0xffffffffu, v, d);
    return v;
}

// h1[nb][j] = relu(bn1(gs[nb] . W1[j] + b1[j])).  grid=H1, block=256 (warp=nb)
__global__ void mlp1_k(const float* __restrict__ W1, const float* __restrict__ b1,
                       const float* __restrict__ g1, const float* __restrict__ be1,
                       const float* __restrict__ rm1, const float* __restrict__ rv1)
{
    const int j    = blockIdx.x;
    const int nb   = threadIdx.x >> 5;
    const int lane = threadIdx.x & 31;

    const float* wr = W1 + (long)j * DSUM;
    const float* gr = g_gs + nb * DSUM;
    float acc = 0.0f;
    #pragma unroll
    for (int it = 0; it < DSUM / 32; it++) {
        const int d = lane + it * 32;
        acc = fmaf(__ldg(gr + d), __ldg(wr + d), acc);
    }
    acc = warp_sum(acc);
    if (lane == 0) {
        acc += __ldg(b1 + j);
        acc = (acc - __ldg(rm1 + j)) * rsqrtf(__ldg(rv1 + j) + 1e-5f) * __ldg(g1 + j) + __ldg(be1 + j);
        g_h1[nb * H1 + j] = fmaxf(acc, 0.0f);
    }
}

// h2[nb][j] = relu(bn2(h1[nb] . W2[j] + b2[j])).  grid=H2, block=256
__global__ void mlp2_k(const float* __restrict__ W2, const float* __restrict__ b2,
                       const float* __restrict__ g2, const float* __restrict__ be2,
                       const float* __restrict__ rm2, const float* __restrict__ rv2)
{
    const int j    = blockIdx.x;
    const int nb   = threadIdx.x >> 5;
    const int lane = threadIdx.x & 31;

    const float* wr = W2 + (long)j * H1;
    const float* hr = g_h1 + nb * H1;
    float acc = 0.0f;
    #pragma unroll
    for (int it = 0; it < H1 / 32; it++) {
        const int d = lane + it * 32;
        acc = fmaf(__ldg(hr + d), __ldg(wr + d), acc);
    }
    acc = warp_sum(acc);
    if (lane == 0) {
        acc += __ldg(b2 + j);
        acc = (acc - __ldg(rm2 + j)) * rsqrtf(__ldg(rv2 + j) + 1e-5f) * __ldg(g2 + j) + __ldg(be2 + j);
        g_h2[nb * H2 + j] = fmaxf(acc, 0.0f);
    }
}

// coeff[nb][j] = h2[nb] . W3[j] + b3[j].  grid=PCA_D, block=256
__global__ void mlp3_k(const float* __restrict__ W3, const float* __restrict__ b3,
                       float* __restrict__ coeff_out)
{
    const int j    = blockIdx.x;
    const int nb   = threadIdx.x >> 5;
    const int lane = threadIdx.x & 31;

    const float* wr = W3 + (long)j * H2;
    const float* hr = g_h2 + nb * H2;
    float acc = 0.0f;
    #pragma unroll
    for (int it = 0; it < H2 / 32; it++) {
        const int d = lane + it * 32;
        acc = fmaf(__ldg(hr + d), __ldg(wr + d), acc);
    }
    acc = warp_sum(acc);
    if (lane == 0) {
        acc += __ldg(b3 + j);
        g_coeff[nb * PCA_D + j]   = acc;
        coeff_out[nb * PCA_D + j] = acc;
    }
}

// ---------------------------------------------------------------------------
// Kernel 4: tpose = (coeff @ pca_comp + mean) * scale.  float2 per thread.
// ---------------------------------------------------------------------------
__global__ void tpose_k(const float* __restrict__ comp,
                        const float* __restrict__ mean,
                        const float* __restrict__ scale,
                        float* __restrict__ out)
{
    __shared__ float sc[NB * PCA_D];
    const int t = threadIdx.x;
    for (int i = t; i < NB * PCA_D; i += 256) sc[i] = g_coeff[i];
    __syncthreads();

    const int d2 = blockIdx.x * 256 + t;
    if (d2 >= V3 / 2) return;
    const int d = d2 * 2;

    float accx[NB], accy[NB];
    #pragma unroll
    for (int nb = 0; nb < NB; nb++) { accx[nb] = 0.0f; accy[nb] = 0.0f; }

    #pragma unroll 4
    for (int k = 0; k < PCA_D; k++) {
        const float2 w = *reinterpret_cast<const float2*>(comp + (long)k * V3 + d);
        #pragma unroll
        for (int nb = 0; nb < NB; nb++) {
            const float c = sc[nb * PCA_D + k];
            accx[nb] = fmaf(c, w.x, accx[nb]);
            accy[nb] = fmaf(c, w.y, accy[nb]);
        }
    }
    const float2 mn = *reinterpret_cast<const float2*>(mean + d);
    const float2 s  = *reinterpret_cast<const float2*>(scale + d);
    #pragma unroll
    for (int nb = 0; nb < NB; nb++) {
        float2 o;
        o.x = (accx[nb] + mn.x) * s.x;
        o.y = (accy[nb] + mn.y) * s.y;
        *reinterpret_cast<float2*>(out + (long)nb * V3 + d) = o;
    }
}

// ---------------------------------------------------------------------------
extern "C" void kernel_launch(void* const* d_in, const int* in_sizes, int n_in,
                              void* d_out, int out_size)
{
    const float* x      = (const float*)d_in[0];
    const float* logits = (const float*)d_in[1];
    const float* feat   = (const float*)d_in[2];
    const float* summ   = (const float*)d_in[3];
    const float* W1  = (const float*)d_in[4];
    const float* b1  = (const float*)d_in[5];
    const float* g1  = (const float*)d_in[6];
    const float* be1 = (const float*)d_in[7];
    const float* rm1 = (const float*)d_in[8];
    const float* rv1 = (const float*)d_in[9];
    const float* W2  = (const float*)d_in[10];
    const float* b2  = (const float*)d_in[11];
    const float* g2  = (const float*)d_in[12];
    const float* be2 = (const float*)d_in[13];
    const float* rm2 = (const float*)d_in[14];
    const float* rv2 = (const float*)d_in[15];
    const float* W3  = (const float*)d_in[16];
    const float* b3  = (const float*)d_in[17];
    const float* comp  = (const float*)d_in[18];
    const float* mean  = (const float*)d_in[19];
    const float* scale = (const float*)d_in[20];
    const int*   glab  = (const int*)d_in[21];

    // Derive n from out_size: out = BT*n*(3+CCH) + NB*PCA_D + NB*V3
    const int n = (out_size - NB * PCA_D - NB * V3) / (BT * (3 + CCH));

    float* gv    = (float*)d_out;
    float* gf    = gv + (long)BT * n * 3;
    float* coeff = gf + (long)BT * n * CCH;
    float* tpose = coeff + NB * PCA_D;

    compact2_k<<<BT, 256>>>(logits, glab, n);
    gather_k<<<dim3((n + 31) / 32, BT), 256>>>(feat, x, gv, gf, n);
    gs_k<<<(NB * DSUM + 255) / 256, 256>>>(summ);
    mlp1_k<<<H1, 256>>>(W1, b1, g1, be1, rm1, rv1);
    mlp2_k<<<H2, 256>>>(W2, b2, g2, be2, rm2, rv2);
    mlp3_k<<<PCA_D, 256>>>(W3, b3, coeff);
    tpose_k<<<(V3 / 2 + 255) / 256, 256>>>(comp, mean, scale, tpose);
}